// round 7
// baseline (speedup 1.0000x reference)
#include <cuda_runtime.h>
#include <math.h>

#define TT 32
#define DD 256
#define HH 768
#define GRIDN 128
#define NT 256

#define OFF_HXLAST (TT*128*HH)
#define OFF_PC     (OFF_HXLAST + 128*HH)
#define OFF_STEPS  (OFF_PC + 128)

typedef unsigned long long ull;

// persistent scratch (allocation-free rule)
__device__ float g_hxi[2][128][HH];               // double-buffered hidden state
__device__ float g_pd[8*128*32];                  // partial ponder dots [n][row][cg]
__device__ __align__(16) unsigned g_flags[GRIDN]; // barrier flags (monotonic)

// x chunk buffer: 32 rows x 41 float4 (32 data + swizzle pad + row pad)
struct SM {
  ull    whh[HH*16];       // [k][16 slots], slot=((c>>1)+2*((k>>4)&7))&15
  ull    wih[DD*16];
  float4 xbuf[2][32*41];   // staged x chunks, 41984 B
  float  hxn[32][26];
  float  ahx[32][26];
  float  wp[24];
  float  ah[128], sc[128], spc[128], coef[128], pc[128];
  int    mask[128];
};

__device__ __forceinline__ ull fma2(ull a, ull b, ull c){
  ull d; asm("fma.rn.f32x2 %0,%1,%2,%3;" : "=l"(d) : "l"(a), "l"(b), "l"(c)); return d;
}
__device__ __forceinline__ ull add2(ull a, ull b){
  ull d; asm("add.rn.f32x2 %0,%1,%2;" : "=l"(d) : "l"(a), "l"(b)); return d;
}
__device__ __forceinline__ ull dup2(float x){
  ull d; unsigned r = __float_as_uint(x);
  asm("mov.b64 %0,{%1,%1};" : "=l"(d) : "r"(r)); return d;
}
__device__ __forceinline__ ull shx64(ull v, int m){
  unsigned lo = (unsigned)v, hi = (unsigned)(v >> 32);
  lo = __shfl_xor_sync(0xffffffffu, lo, m);
  hi = __shfl_xor_sync(0xffffffffu, hi, m);
  return ((ull)hi << 32) | lo;
}

// flag-based grid barrier
__device__ __forceinline__ void gbar(unsigned ep){
  __syncthreads();
  if (threadIdx.x == 0)
    asm volatile("st.release.gpu.global.u32 [%0], %1;"
                 :: "l"(&g_flags[blockIdx.x]), "r"(ep) : "memory");
  if (threadIdx.x < 32){
    const unsigned* fp = g_flags + threadIdx.x*4;
    for(;;){
      unsigned a,b,c,d;
      asm volatile("ld.relaxed.gpu.global.v4.u32 {%0,%1,%2,%3}, [%4];"
                   : "=r"(a),"=r"(b),"=r"(c),"=r"(d) : "l"(fp) : "memory");
      if ((int)(a-ep)>=0 && (int)(b-ep)>=0 && (int)(c-ep)>=0 && (int)(d-ep)>=0) break;
    }
    asm volatile("fence.acq_rel.gpu;" ::: "memory");
  }
  __syncthreads();
}

__device__ __forceinline__ void cpasync16(void* dst, const void* src){
  unsigned d = (unsigned)__cvta_generic_to_shared(dst);
  asm volatile("cp.async.cg.shared.global [%0], [%1], 16;" :: "r"(d), "l"(src));
}

// stage one 32x128-float chunk into xbuf (swizzled): 4 cp.async per thread
__device__ __forceinline__ void stage_chunk(float4* xb, const float* gbase,
                                            int gstride, int c, int tid){
  #pragma unroll
  for (int i = 0; i < 4; i++){
    int idx = tid + i*NT;              // 0..1023
    int row = idx >> 5, kq = idx & 31;
    const float* src = gbase + (size_t)row*gstride + c*128 + kq*4;
    float4* dst = xb + row*41 + kq + (kq >> 2);
    cpasync16(dst, src);
  }
  asm volatile("cp.async.commit_group;");
}

// compute one chunk: thread = 4 rows x 3 pairs, 16 k's (kl slice)
__device__ __forceinline__ void compute_chunk(ull (&acc)[12], const float4* xb,
    const ull* w0, const ull* w1, const ull* w2, int r0t, int kl){
  const float4* xp = xb + r0t*41 + 5*kl;
  float4 xc[4], xn[4];
  #pragma unroll
  for (int r = 0; r < 4; r++) xc[r] = xp[r*41];
  #pragma unroll
  for (int j = 0; j < 4; j++){
    if (j < 3){
      #pragma unroll
      for (int r = 0; r < 4; r++) xn[r] = xp[r*41 + j + 1];
    }
    #pragma unroll
    for (int jj = 0; jj < 4; jj++){
      int ko = (j*4 + jj)*16;
      ull wa = w0[ko], wb = w1[ko], wc = w2[ko];
      #pragma unroll
      for (int r = 0; r < 4; r++){
        ull xd = dup2(((const float*)&xc[r])[jj]);
        acc[r*3+0] = fma2(xd, wa, acc[r*3+0]);
        acc[r*3+1] = fma2(xd, wb, acc[r*3+1]);
        acc[r*3+2] = fma2(xd, wc, acc[r*3+2]);
      }
    }
    #pragma unroll
    for (int r = 0; r < 4; r++) xc[r] = xn[r];
  }
}

// full GEMM: NC chunks of K=128, double-buffered cp.async pipeline
template<int NC>
__device__ __forceinline__ void gemm_smem(ull (&acc)[12], SM& s,
    const float* gbase, int gstride, const ull* wb,
    int off0, int off1, int off2, int tid, int kl, int r0t){
  stage_chunk(&s.xbuf[0][0], gbase, gstride, 0, tid);
  #pragma unroll
  for (int c = 0; c < NC; c++){
    if (c + 1 < NC){
      stage_chunk(&s.xbuf[(c+1)&1][0], gbase, gstride, c+1, tid);
      asm volatile("cp.async.wait_group 1;");
    } else {
      asm volatile("cp.async.wait_group 0;");
    }
    __syncthreads();
    const ull* wk = wb + (size_t)(c*128 + kl*16)*16;
    compute_chunk(acc, &s.xbuf[c&1][0], wk+off0, wk+off1, wk+off2, r0t, kl);
    __syncthreads();
  }
}

__device__ __forceinline__ void reduce12(ull (&acc)[12]){
  #pragma unroll
  for (int p = 0; p < 12; ++p){
    acc[p] = add2(acc[p], shx64(acc[p],1));
    acc[p] = add2(acc[p], shx64(acc[p],2));
    acc[p] = add2(acc[p], shx64(acc[p],4));
  }
}

__global__ void __launch_bounds__(NT, 1)
act_kernel(const float* __restrict__ input, const float* __restrict__ Wih,
           const float* __restrict__ Whh, const float* __restrict__ bih,
           const float* __restrict__ bhh, const float* __restrict__ wpv,
           const float* __restrict__ bpv, float* __restrict__ out)
{
  extern __shared__ unsigned char smraw[];
  SM& s = *reinterpret_cast<SM*>(smraw);
  const int tid = threadIdx.x, blk = blockIdx.x;
  const int rg = blk >> 5, cg = blk & 31;
  const int row0 = rg*32, col0 = cg*24;
  const int lane = tid & 31, warp = tid >> 5;
  const int kl = lane & 7, u = lane >> 3;
  const int phh = warp >> 2;             // pair half (0/1)
  const int wrow = (warp & 3) * 8;       // warp row base
  const int u_row = u & 1, u_tri = u >> 1;
  const int r0t = wrow + u_row*4;        // thread's 4 local rows start
  const int p0  = phh*6 + u_tri*3;       // block-local pair base (0,3,6,9)

  const int off0 = (p0 + 0 + 2*kl) & 15;
  const int off1 = (p0 + 1 + 2*kl) & 15;
  const int off2 = (p0 + 2 + 2*kl) & 15;

  // ---- one-time: stage weights, rotation keyed to (k>>4)&7 ----
  for (int idx = tid; idx < 24*HH; idx += NT){
    int c = idx / HH, k = idx - c*HH;
    int slot = ((c >> 1) + 2*((k>>4)&7)) & 15;
    ((float*)&s.whh[(size_t)k*16 + slot])[c & 1] = Whh[(size_t)(col0+c)*HH + k];
  }
  for (int idx = tid; idx < 24*DD; idx += NT){
    int c = idx / DD, k = idx - c*DD;
    int slot = ((c >> 1) + 2*((k>>4)&7)) & 15;
    ((float*)&s.wih[(size_t)k*16 + slot])[c & 1] = Wih[(size_t)(col0+c)*(DD+1) + k];
  }
  if (tid < 24) s.wp[tid] = wpv[col0+tid];
  if (tid < 128) s.pc[tid] = 0.f;
  for (int e = tid; e < 32*24; e += NT){
    int r2 = e/24, c2 = e - r2*24;
    g_hxi[0][row0+r2][col0+c2] = 0.f;
  }

  // epilogue-thread registers: coords, flag weights, biases
  int rrA=0, ccA=0, rrB=0, ccB=0;
  float flwA0=0,flwA1=0,flwB0=0,flwB1=0;
  float bsA0=0,bsA1=0,bsB0=0,bsB1=0;
  if (kl < 6){
    int idxA = kl*2, idxB = kl*2 + 1;
    int rA = idxA/3, mA = idxA - rA*3;
    int rB = idxB/3, mB = idxB - rB*3;
    rrA = r0t + rA; ccA = (p0 + mA)*2;
    rrB = r0t + rB; ccB = (p0 + mB)*2;
    flwA0 = Wih[(size_t)(col0+ccA  )*(DD+1) + DD];
    flwA1 = Wih[(size_t)(col0+ccA+1)*(DD+1) + DD];
    flwB0 = Wih[(size_t)(col0+ccB  )*(DD+1) + DD];
    flwB1 = Wih[(size_t)(col0+ccB+1)*(DD+1) + DD];
    bsA0 = bih[col0+ccA  ] + bhh[col0+ccA  ];
    bsA1 = bih[col0+ccA+1] + bhh[col0+ccA+1];
    bsB0 = bih[col0+ccB  ] + bhh[col0+ccB  ];
    bsB1 = bih[col0+ccB+1] + bhh[col0+ccB+1];
  }
  const float bp0 = bpv[0];
  int rb = 0;
  unsigned ep = g_flags[blk];
  gbar(++ep);

  for (int t = 0; t < TT; ++t){
    if (tid < 128){ s.ah[tid]=0.f; s.sc[tid]=0.f; s.spc[tid]=0.f; s.mask[tid]=1; }
    for (int e = tid; e < 32*24; e += NT){ int r2=e/24, c2=e-r2*24; s.ahx[r2][c2]=0.f; }
    __syncthreads();

    // ---- base = x_t @ W_ih^T + biases (register-resident) ----
    float baseA0=0, baseA1=0, baseB0=0, baseB1=0;
    {
      ull acc[12] = {0,0,0,0,0,0,0,0,0,0,0,0};
      gemm_smem<2>(acc, s, input + ((size_t)t*128 + row0)*DD, DD,
                   s.wih, off0, off1, off2, tid, kl, r0t);
      reduce12(acc);
      if (kl < 6){
        int idxA = kl*2, idxB = kl*2 + 1;
        float2 fA = *(float2*)&acc[idxA];
        float2 fB = *(float2*)&acc[idxB];
        baseA0 = fA.x + bsA0; baseA1 = fA.y + bsA1;
        baseB0 = fB.x + bsB0; baseB1 = fB.y + bsB1;
      }
    }
    __syncthreads();

    // ---- ponder loop ----
    for (int n = 0; n < 8; ++n){
      ull acc[12] = {0,0,0,0,0,0,0,0,0,0,0,0};
      gemm_smem<6>(acc, s, &g_hxi[rb][row0][0], HH,
                   s.whh, off0, off1, off2, tid, kl, r0t);
      reduce12(acc);

      const float fl = (n == 0) ? 0.f : 1.f;
      if (kl < 6){
        int idxA = kl*2, idxB = kl*2 + 1;
        float2 fA = *(float2*)&acc[idxA];
        float2 fB = *(float2*)&acc[idxB];
        float hA0 = tanhf(fA.x + baseA0 + fl*flwA0);
        float hA1 = tanhf(fA.y + baseA1 + fl*flwA1);
        float hB0 = tanhf(fB.x + baseB0 + fl*flwB0);
        float hB1 = tanhf(fB.y + baseB1 + fl*flwB1);
        s.hxn[rrA][ccA] = hA0; s.hxn[rrA][ccA+1] = hA1;
        s.hxn[rrB][ccB] = hB0; s.hxn[rrB][ccB+1] = hB1;
        int grA = row0 + rrA, gcA = col0 + ccA;
        int grB = row0 + rrB, gcB = col0 + ccB;
        float2 oA, oB;
        if (s.mask[grA]) oA = make_float2(hA0,hA1);
        else             oA = __ldcg((const float2*)&g_hxi[rb][grA][gcA]);
        if (s.mask[grB]) oB = make_float2(hB0,hB1);
        else             oB = __ldcg((const float2*)&g_hxi[rb][grB][gcB]);
        *(float2*)&g_hxi[rb^1][grA][gcA] = oA;
        *(float2*)&g_hxi[rb^1][grB][gcB] = oB;
      }
      __syncthreads();
      if (tid < 32){
        float pd = 0.f;
        #pragma unroll
        for (int c = 0; c < 24; c++) pd = fmaf(s.hxn[tid][c], s.wp[c], pd);
        g_pd[(size_t)(n*128 + row0 + tid)*32 + cg] = pd;
      }
      gbar(++ep);

      // redundant identical scalar update (fixed order => identical everywhere)
      int nm = 0;
      if (tid < 128){
        const float4* pr4 = (const float4*)&g_pd[(size_t)(n*128 + tid)*32];
        float sum = 0.f;
        #pragma unroll
        for (int q = 0; q < 8; q++){
          float4 v4 = __ldcg(pr4 + q);
          sum += v4.x; sum += v4.y; sum += v4.z; sum += v4.w;
        }
        float h = 1.f/(1.f + expf(-(sum + bp0)));
        int   m  = s.mask[tid];
        float mf = m ? 1.f : 0.f;
        if (m) s.spc[tid] = -s.ah[tid];
        float ah2 = s.ah[tid] + mf*h;
        float p2  = h - fmaxf(ah2 - 1.f, 0.f);
        s.coef[tid] = mf*(1.f + p2);
        s.sc[tid]  += mf;
        s.ah[tid]   = ah2;
        int m2 = (ah2 < 0.99f);
        s.mask[tid] = m2;
        nm = m2;
      }
      int nlive = __syncthreads_or(nm);
      for (int e = tid; e < 32*24; e += NT){
        int r2 = e/24, c2 = e - r2*24;
        s.ahx[r2][c2] = fmaf(s.coef[row0+r2], s.hxn[r2][c2], s.ahx[r2][c2]);
      }
      __syncthreads();
      rb ^= 1;
      if (!nlive) break;
    }

    // ---- end of step: outputs + carry ----
    for (int e = tid; e < 32*24; e += NT){
      int r2 = e/24, c2 = e - r2*24;
      int gr2 = row0 + r2, gc2 = col0 + c2;
      float v = s.ahx[r2][c2] / s.sc[gr2];
      out[(size_t)(t*128 + gr2)*HH + gc2] = v;
      if (t == TT-1) out[OFF_HXLAST + (size_t)gr2*HH + gc2] = v;
      g_hxi[rb][gr2][gc2] = v;
    }
    if (blk == 0 && tid < 128){
      s.pc[tid] += s.spc[tid];
      out[OFF_STEPS + t*128 + tid] = s.sc[tid];
    }
    gbar(++ep);
  }

  if (blk == 0 && tid < 128) out[OFF_PC + tid] = s.pc[tid];
}

extern "C" void kernel_launch(void* const* d_in, const int* in_sizes, int n_in,
                              void* d_out, int out_size)
{
  const float* input = (const float*)d_in[0];
  const float* Wih   = (const float*)d_in[1];
  const float* Whh   = (const float*)d_in[2];
  const float* bih   = (const float*)d_in[3];
  const float* bhh   = (const float*)d_in[4];
  const float* wpv   = (const float*)d_in[5];
  const float* bpv   = (const float*)d_in[6];
  (void)in_sizes; (void)n_in; (void)out_size;

  cudaFuncSetAttribute(act_kernel, cudaFuncAttributeMaxDynamicSharedMemorySize, (int)sizeof(SM));
  act_kernel<<<GRIDN, NT, sizeof(SM)>>>(input, Wih, Whh, bih, bhh, wpv, bpv, (float*)d_out);
}

// round 9
// speedup vs baseline: 1.6287x; 1.6287x over previous
#include <cuda_runtime.h>
#include <math.h>

#define TT 32
#define DD 256
#define HH 768
#define GRIDN 128
#define NT 512

#define OFF_HXLAST (TT*128*HH)
#define OFF_PC     (OFF_HXLAST + 128*HH)
#define OFF_STEPS  (OFF_PC + 128)

#define WSTR_H 388   // 384 data ulls + pad per pair (whh buckets)
#define WSTR_I 132   // 128 data ulls + pad per pair (wih buckets)

typedef unsigned long long ull;

// persistent scratch (allocation-free rule)
__device__ float g_hxi[2][128][HH];               // double-buffered hidden state
__device__ float g_pd[8*128*32];                  // partial ponder dots [n][row][cg]
__device__ __align__(16) unsigned g_flags[GRIDN]; // barrier flags (monotonic)

struct SM {
  ull   whhA[12*WSTR_H];  // pair-packed weights, k%4 in {0,1}
  ull   whhB[12*WSTR_H];  // k%4 in {2,3}
  ull   wihA[12*WSTR_I];
  ull   wihB[12*WSTR_I];
  float hxn[32][26];
  float ahx[32][26];
  float wp[24];
  float ah[128], sc[128], spc[128], coef[128], pc[128];
  int   mask[128];
};

__device__ __forceinline__ ull fma2(ull a, ull b, ull c){
  ull d; asm("fma.rn.f32x2 %0,%1,%2,%3;" : "=l"(d) : "l"(a), "l"(b), "l"(c)); return d;
}
__device__ __forceinline__ ull add2(ull a, ull b){
  ull d; asm("add.rn.f32x2 %0,%1,%2;" : "=l"(d) : "l"(a), "l"(b)); return d;
}
__device__ __forceinline__ ull dup2(float x){
  ull d; unsigned r = __float_as_uint(x);
  asm("mov.b64 %0,{%1,%1};" : "=l"(d) : "r"(r)); return d;
}
__device__ __forceinline__ ull shx64(ull v, int m){
  unsigned lo = (unsigned)v, hi = (unsigned)(v >> 32);
  lo = __shfl_xor_sync(0xffffffffu, lo, m);
  hi = __shfl_xor_sync(0xffffffffu, hi, m);
  return ((ull)hi << 32) | lo;
}

// flag-based grid barrier: 1 release STG arrival, 32 pollers x 4 flags
__device__ __forceinline__ void gbar(unsigned ep){
  __syncthreads();
  if (threadIdx.x == 0)
    asm volatile("st.release.gpu.global.u32 [%0], %1;"
                 :: "l"(&g_flags[blockIdx.x]), "r"(ep) : "memory");
  if (threadIdx.x < 32){
    const unsigned* fp = g_flags + threadIdx.x*4;
    for(;;){
      unsigned a,b,c,d;
      asm volatile("ld.relaxed.gpu.global.v4.u32 {%0,%1,%2,%3}, [%4];"
                   : "=r"(a),"=r"(b),"=r"(c),"=r"(d) : "l"(fp) : "memory");
      if ((int)(a-ep)>=0 && (int)(b-ep)>=0 && (int)(c-ep)>=0 && (int)(d-ep)>=0) break;
    }
    asm volatile("fence.acq_rel.gpu;" ::: "memory");
  }
  __syncthreads();
}

// GEMM: warp = 4 rows x 6 pairs, lanes split K 32-way (contiguous float4 per lane).
// acc[i], i = r*6 + p. NIT = K/128 chunks. CG: hx from L2 (cross-block).
// Wa/Wb must already include the warp's pair-group offset (p0*WSTR).
template<int NIT, int WSTR, bool CG>
__device__ __forceinline__ void gemmJ(ull (&acc)[24],
    const float* xrow0, int xstride,
    const ull* Wa, const ull* Wb, int lane)
{
  const float4* xq[4];
  #pragma unroll
  for (int r = 0; r < 4; r++) xq[r] = (const float4*)(xrow0 + r*xstride);

  float4 xc[4], xn[4];
  #pragma unroll
  for (int r = 0; r < 4; r++)
    xc[r] = CG ? __ldcg(xq[r] + lane) : __ldg(xq[r] + lane);

  #pragma unroll
  for (int it = 0; it < NIT; ++it){
    if (it + 1 < NIT){
      #pragma unroll
      for (int r = 0; r < 4; r++)
        xn[r] = CG ? __ldcg(xq[r] + (it+1)*32 + lane) : __ldg(xq[r] + (it+1)*32 + lane);
    }
    const int kofs = (it*32 + lane)*2;
    // jh = 0: k0,k0+1 from bucket A; jh = 1: k0+2,k0+3 from bucket B
    #pragma unroll
    for (int jh = 0; jh < 2; jh++){
      ull xd[8];
      #pragma unroll
      for (int r = 0; r < 4; r++){
        const float* xf = (const float*)&xc[r];
        xd[r*2+0] = dup2(xf[jh*2+0]);
        xd[r*2+1] = dup2(xf[jh*2+1]);
      }
      const ull* W = jh ? Wb : Wa;
      #pragma unroll
      for (int p = 0; p < 6; p++){
        ulonglong2 w = *(const ulonglong2*)(W + (size_t)p*WSTR + kofs);
        #pragma unroll
        for (int r = 0; r < 4; r++){
          acc[r*6+p] = fma2(xd[r*2+0], w.x, acc[r*6+p]);
          acc[r*6+p] = fma2(xd[r*2+1], w.y, acc[r*6+p]);
        }
      }
    }
    #pragma unroll
    for (int r = 0; r < 4; r++) xc[r] = xn[r];
  }
}

__device__ __forceinline__ void reduce24(ull (&acc)[24]){
  #pragma unroll
  for (int i = 0; i < 24; ++i){
    acc[i] = add2(acc[i], shx64(acc[i],16));
    acc[i] = add2(acc[i], shx64(acc[i],8));
    acc[i] = add2(acc[i], shx64(acc[i],4));
    acc[i] = add2(acc[i], shx64(acc[i],2));
    acc[i] = add2(acc[i], shx64(acc[i],1));
  }
}

__global__ void __launch_bounds__(NT, 1)
act_kernel(const float* __restrict__ input, const float* __restrict__ Wih,
           const float* __restrict__ Whh, const float* __restrict__ bih,
           const float* __restrict__ bhh, const float* __restrict__ wpv,
           const float* __restrict__ bpv, float* __restrict__ out)
{
  extern __shared__ unsigned char smraw[];
  SM& s = *reinterpret_cast<SM*>(smraw);
  const int tid = threadIdx.x, blk = blockIdx.x;
  const int rg = blk >> 5, cg = blk & 31;
  const int row0 = rg*32, col0 = cg*24;
  const int lane = tid & 31, warp = tid >> 5;
  const int rg2  = warp & 7;         // 8 row groups of 4 rows
  const int cgrp = warp >> 3;        // 2 col groups of 6 pairs
  const int r0w  = rg2*4;
  const int p0   = cgrp*6;

  // warp's weight bases (FIX vs R7: apply p0 offset here)
  const ull* whhA_w = s.whhA + (size_t)p0*WSTR_H;
  const ull* whhB_w = s.whhB + (size_t)p0*WSTR_H;
  const ull* wihA_w = s.wihA + (size_t)p0*WSTR_I;
  const ull* wihB_w = s.wihB + (size_t)p0*WSTR_I;

  // ---- one-time: stage weights pair-packed into A/B buckets ----
  // bucket sel = (k>>1)&1 ; idx = p*WSTR + 2*(k>>2) + (k&1) ; float slot = c&1
  for (int idx = tid; idx < 24*HH; idx += NT){
    int c = idx / HH, k = idx - c*HH;
    int p = c >> 1;
    ull* base = ((k >> 1) & 1) ? s.whhB : s.whhA;
    size_t e = (size_t)p*WSTR_H + 2*(k>>2) + (k&1);
    ((float*)&base[e])[c & 1] = Whh[(size_t)(col0+c)*HH + k];
  }
  for (int idx = tid; idx < 24*DD; idx += NT){
    int c = idx / DD, k = idx - c*DD;
    int p = c >> 1;
    ull* base = ((k >> 1) & 1) ? s.wihB : s.wihA;
    size_t e = (size_t)p*WSTR_I + 2*(k>>2) + (k&1);
    ((float*)&base[e])[c & 1] = Wih[(size_t)(col0+c)*(DD+1) + k];
  }
  if (tid < 24) s.wp[tid] = wpv[col0+tid];
  if (tid < 128) s.pc[tid] = 0.f;
  for (int e = tid; e < 32*24; e += NT){
    int r2 = e/24, c2 = e - r2*24;
    g_hxi[0][row0+r2][col0+c2] = 0.f;
  }

  // epilogue lane (lane<24) registers: i = lane = r*6+p
  int rr = 0, cc = 0;
  float flw0=0, flw1=0, bs0=0, bs1=0;
  if (lane < 24){
    int r = lane / 6, p = lane - r*6;
    rr = r0w + r;
    cc = (p0 + p)*2;
    flw0 = Wih[(size_t)(col0+cc  )*(DD+1) + DD];
    flw1 = Wih[(size_t)(col0+cc+1)*(DD+1) + DD];
    bs0  = bih[col0+cc  ] + bhh[col0+cc  ];
    bs1  = bih[col0+cc+1] + bhh[col0+cc+1];
  }
  const float bp0 = bpv[0];
  int rb = 0;
  unsigned ep = g_flags[blk];   // epoch persists across graph replays
  gbar(++ep);

  for (int t = 0; t < TT; ++t){
    if (tid < 128){ s.ah[tid]=0.f; s.sc[tid]=0.f; s.spc[tid]=0.f; s.mask[tid]=1; }
    for (int e = tid; e < 32*24; e += NT){ int r2=e/24, c2=e-r2*24; s.ahx[r2][c2]=0.f; }
    __syncthreads();

    // ---- base = x_t @ W_ih^T + biases (register-resident) ----
    float base0 = 0.f, base1 = 0.f;
    {
      ull acc[24];
      #pragma unroll
      for (int i = 0; i < 24; i++) acc[i] = 0ull;
      gemmJ<2, WSTR_I, false>(acc, input + ((size_t)t*128 + row0 + r0w)*DD, DD,
                              wihA_w, wihB_w, lane);
      reduce24(acc);
      if (lane < 24){
        float2 f = *(float2*)&acc[lane];
        base0 = f.x + bs0;
        base1 = f.y + bs1;
      }
    }
    __syncthreads();

    // ---- ponder loop ----
    for (int n = 0; n < 8; ++n){
      ull acc[24];
      #pragma unroll
      for (int i = 0; i < 24; i++) acc[i] = 0ull;
      gemmJ<6, WSTR_H, true>(acc, &g_hxi[rb][row0 + r0w][0], HH,
                             whhA_w, whhB_w, lane);
      reduce24(acc);

      const float fl = (n == 0) ? 0.f : 1.f;
      if (lane < 24){
        float2 f = *(float2*)&acc[lane];
        float h0 = tanhf(f.x + base0 + fl*flw0);
        float h1 = tanhf(f.y + base1 + fl*flw1);
        s.hxn[rr][cc]   = h0;
        s.hxn[rr][cc+1] = h1;
        int gr = row0 + rr, gc = col0 + cc;
        float2 o;
        if (s.mask[gr]) o = make_float2(h0, h1);
        else            o = __ldcg((const float2*)&g_hxi[rb][gr][gc]);
        *(float2*)&g_hxi[rb^1][gr][gc] = o;
      }
      __syncthreads();
      if (tid < 32){
        float pd = 0.f;
        #pragma unroll
        for (int c = 0; c < 24; c++) pd = fmaf(s.hxn[tid][c], s.wp[c], pd);
        g_pd[(size_t)(n*128 + row0 + tid)*32 + cg] = pd;
      }
      gbar(++ep);

      // redundant identical scalar update (fixed order => identical everywhere)
      int nm = 0;
      if (tid < 128){
        const float4* pr4 = (const float4*)&g_pd[(size_t)(n*128 + tid)*32];
        float sum = 0.f;
        #pragma unroll
        for (int q = 0; q < 8; q++){
          float4 v4 = __ldcg(pr4 + q);
          sum += v4.x; sum += v4.y; sum += v4.z; sum += v4.w;
        }
        float h = 1.f/(1.f + expf(-(sum + bp0)));
        int   m  = s.mask[tid];
        float mf = m ? 1.f : 0.f;
        if (m) s.spc[tid] = -s.ah[tid];
        float ah2 = s.ah[tid] + mf*h;
        float p2  = h - fmaxf(ah2 - 1.f, 0.f);
        s.coef[tid] = mf*(1.f + p2);
        s.sc[tid]  += mf;
        s.ah[tid]   = ah2;
        int m2 = (ah2 < 0.99f);
        s.mask[tid] = m2;
        nm = m2;
      }
      int nlive = __syncthreads_or(nm);
      for (int e = tid; e < 32*24; e += NT){
        int r2 = e/24, c2 = e - r2*24;
        s.ahx[r2][c2] = fmaf(s.coef[row0+r2], s.hxn[r2][c2], s.ahx[r2][c2]);
      }
      __syncthreads();
      rb ^= 1;
      if (!nlive) break;
    }

    // ---- end of step: outputs + carry ----
    for (int e = tid; e < 32*24; e += NT){
      int r2 = e/24, c2 = e - r2*24;
      int gr2 = row0 + r2, gc2 = col0 + c2;
      float v = s.ahx[r2][c2] / s.sc[gr2];
      out[(size_t)(t*128 + gr2)*HH + gc2] = v;
      if (t == TT-1) out[OFF_HXLAST + (size_t)gr2*HH + gc2] = v;
      g_hxi[rb][gr2][gc2] = v;
    }
    if (blk == 0 && tid < 128){
      s.pc[tid] += s.spc[tid];
      out[OFF_STEPS + t*128 + tid] = s.sc[tid];
    }
    gbar(++ep);
  }

  if (blk == 0 && tid < 128) out[OFF_PC + tid] = s.pc[tid];
}

extern "C" void kernel_launch(void* const* d_in, const int* in_sizes, int n_in,
                              void* d_out, int out_size)
{
  const float* input = (const float*)d_in[0];
  const float* Wih   = (const float*)d_in[1];
  const float* Whh   = (const float*)d_in[2];
  const float* bih   = (const float*)d_in[3];
  const float* bhh   = (const float*)d_in[4];
  const float* wpv   = (const float*)d_in[5];
  const float* bpv   = (const float*)d_in[6];
  (void)in_sizes; (void)n_in; (void)out_size;

  cudaFuncSetAttribute(act_kernel, cudaFuncAttributeMaxDynamicSharedMemorySize, (int)sizeof(SM));
  act_kernel<<<GRIDN, NT, sizeof(SM)>>>(input, Wih, Whh, bih, bhh, wpv, bpv, (float*)d_out);
}